// round 2
// baseline (speedup 1.0000x reference)
#include <cuda_runtime.h>

#define BB 2
#define NN 1024
#define CC 256
#define PP 256
#define KPP 27
#define NS 16
#define H1 128
#define H2 64
#define H3 32
#define MTOT (H3*KPP)          // 864
#define RADIUS 0.2f
#define KP_PER_B (PP*KPP)      // 6912
#define KP_TOTAL (BB*KP_PER_B) // 13824

// ---- scratch (no allocation allowed -> device globals) ----
__device__ float g_F1[BB*NN*H1];          // precomputed feature @ W1[3:] + b1
__device__ float g_kpts[KP_TOTAL*3];
__device__ int   g_idx[KP_TOTAL*NS];
__device__ int   g_cnt[KP_TOTAL];
__device__ float g_pool[BB*PP*H3*KPP];    // [b][p][c][k] == f[b][p][m], m=c*27+k

// ============================================================
// K1: F1[b][n][j] = sum_c feat[b][c][n] * W1[3+c][j] + b1[j]
// 64x64 tile, k-chunks of 32, 4x4 register tile, 256 threads
// grid = 2b * 16 ntiles * 2 jtiles = 64 blocks
// ============================================================
__global__ void k1_f1(const float* __restrict__ feat,
                      const float* __restrict__ W1,
                      const float* __restrict__ b1) {
    __shared__ __align__(16) float As[32][64];
    __shared__ __align__(16) float Bs[32][64];
    int bx = blockIdx.x;
    int b  = bx >> 5;
    int nt = (bx & 31) >> 1;
    int jt = bx & 1;
    int n0 = nt * 64, j0 = jt * 64;
    int t  = threadIdx.x;
    int tr = t >> 4, tc = t & 15;
    float acc[4][4] = {};

    for (int c0 = 0; c0 < CC; c0 += 32) {
        __syncthreads();
#pragma unroll
        for (int i = 0; i < 8; i++) {
            int e  = t + 256 * i;
            int cc = e >> 6, nn = e & 63;
            As[cc][nn] = feat[(size_t)b*CC*NN + (size_t)(c0+cc)*NN + n0 + nn];
            Bs[cc][nn] = W1[(size_t)(3 + c0 + cc)*H1 + j0 + nn];
        }
        __syncthreads();
#pragma unroll
        for (int kk = 0; kk < 32; kk++) {
            float4 a = *(const float4*)&As[kk][tr*4];
            float4 w = *(const float4*)&Bs[kk][tc*4];
            float av[4] = {a.x,a.y,a.z,a.w};
            float wv[4] = {w.x,w.y,w.z,w.w};
#pragma unroll
            for (int r = 0; r < 4; r++)
#pragma unroll
                for (int q = 0; q < 4; q++) acc[r][q] += av[r]*wv[q];
        }
    }
#pragma unroll
    for (int r = 0; r < 4; r++) {
        int n = n0 + tr*4 + r;
#pragma unroll
        for (int q = 0; q < 4; q++) {
            int j = j0 + tc*4 + q;
            g_F1[((size_t)b*NN + n)*H1 + j] = acc[r][q] + b1[j];
        }
    }
}

// ============================================================
// K2: grid keypoints + ball query (first cnt<=16 in-ball seeds,
// in index order == smallest indices == reference top_k result)
// warp per keypoint, 8 warps/block, seeds staged in smem
// grid = KP_TOTAL/8 = 1728 blocks
// ============================================================
__global__ void k2_ballquery(const float* __restrict__ seed_xyz,
                             const float* __restrict__ boxes,
                             const float* __restrict__ origins,
                             const float* __restrict__ heading) {
    __shared__ float sx[NN], sy[NN], sz[NN], ssq[NN];
    int b      = blockIdx.x / (KP_PER_B / 8);
    int kpbase = (blockIdx.x % (KP_PER_B / 8)) * 8;
    int t = threadIdx.x;
    for (int i = t; i < NN; i += 256) {
        float x = seed_xyz[((size_t)b*NN + i)*3 + 0];
        float y = seed_xyz[((size_t)b*NN + i)*3 + 1];
        float z = seed_xyz[((size_t)b*NN + i)*3 + 2];
        sx[i]=x; sy[i]=y; sz[i]=z; ssq[i]=x*x+y*y+z*z;
    }
    __syncthreads();

    int w = t >> 5, lane = t & 31;
    int kpid = kpbase + w;
    int g = b*KP_PER_B + kpid;
    int p = kpid / KPP, k = kpid % KPP;

    const float* bx = boxes + ((size_t)b*PP + p)*6;
    float b0=bx[0], b1v=bx[1], b2v=bx[2], b3v=bx[3], b4v=bx[4], b5v=bx[5];
    const float* og = origins + ((size_t)b*PP + p)*3;
    float h = heading[(size_t)b*PP + p];
    int i0 = k/9, i1 = (k/3)%3, i2 = k%3;
    float lx = (i0+0.5f)/3.0f*(b0+b3v) - b0;
    float ly = (i1+0.5f)/3.0f*(b1v+b4v) - b1v;
    float lz = (i2+0.5f)/3.0f*(b2v+b5v) - b2v;
    float ch = cosf(h), sh = sinf(h);
    float px =  lx*ch + ly*sh + og[0];
    float py = -lx*sh + ly*ch + og[1];
    float pz =  lz + og[2];

    float kn2 = px*px + py*py + pz*pz;
    const float r2 = RADIUS*RADIUS;
    unsigned total = 0;
    for (int base = 0; base < NN; base += 32) {
        int n = base + lane;
        // match reference: |k|^2 + |s|^2 - 2 k.s
        float d2 = kn2 + ssq[n] - 2.0f*(px*sx[n] + py*sy[n] + pz*sz[n]);
        bool in = d2 < r2;
        unsigned m = __ballot_sync(0xffffffffu, in);
        if (m && total < 16u) {
            int before = __popc(m & ((1u << lane) - 1u));
            if (in && total + before < 16u)
                g_idx[g*NS + total + before] = n;
        }
        total += __popc(m);
        if (total >= 16u) break;
    }
    if (lane == 0) {
        int stored = total < 16u ? (int)total : 16;
        if (stored == 0) { g_idx[g*NS] = 0; stored = 1; }  // reference fill -> seed 0
        g_cnt[g] = stored;
        g_kpts[g*3+0] = px; g_kpts[g*3+1] = py; g_kpts[g*3+2] = pz;
    }
}

// ============================================================
// K3: fused MLP (gathered layer1 + L2 + L3) + max over samples
// warp per keypoint; W2/W3 in smem; only cnt real samples
// grid = 1728 blocks x 256 threads
// ============================================================
__global__ void k3_mlp(const float* __restrict__ seed_xyz,
                       const float* __restrict__ W1,
                       const float* __restrict__ W2,
                       const float* __restrict__ b2,
                       const float* __restrict__ W3,
                       const float* __restrict__ b3) {
    __shared__ __align__(16) float W2s[H1*H2];   // 32 KB
    __shared__ __align__(16) float W3s[H2*H3];   // 8 KB
    __shared__ __align__(16) float h1s[8][H1];   // 4 KB
    __shared__ __align__(16) float h2s[8][H2];   // 2 KB
    int t = threadIdx.x;
    for (int i = t; i < H1*H2; i += 256) W2s[i] = W2[i];
    for (int i = t; i < H2*H3; i += 256) W3s[i] = W3[i];
    __syncthreads();

    int w = t >> 5, lane = t & 31;
    int g = blockIdx.x * 8 + w;
    int b = g / KP_PER_B;
    int kpid = g % KP_PER_B;
    int p = kpid / KPP, k = kpid % KPP;

    float kx = g_kpts[g*3+0], ky = g_kpts[g*3+1], kz = g_kpts[g*3+2];
    int cnt = g_cnt[g];

    float w1x[4], w1y[4], w1z[4];
#pragma unroll
    for (int m2 = 0; m2 < 4; m2++) {
        int j = lane + 32*m2;
        w1x[m2] = W1[0*H1 + j];
        w1y[m2] = W1[1*H1 + j];
        w1z[m2] = W1[2*H1 + j];
    }
    float bb2a = b2[lane], bb2b = b2[lane+32];
    float bb3  = b3[lane];
    const float invR = 1.0f / RADIUS;
    float mx = -1e30f;

    for (int s = 0; s < cnt; s++) {
        int i = g_idx[g*NS + s];
        const float* sp = seed_xyz + ((size_t)b*NN + i)*3;
        float gx = (sp[0] - kx) * invR;
        float gy = (sp[1] - ky) * invR;
        float gz = (sp[2] - kz) * invR;
        const float* f1p = &g_F1[((size_t)b*NN + i)*H1];
#pragma unroll
        for (int m2 = 0; m2 < 4; m2++) {
            int j = lane + 32*m2;
            float v = f1p[j] + gx*w1x[m2] + gy*w1y[m2] + gz*w1z[m2];
            h1s[w][j] = fmaxf(v, 0.0f);
        }
        __syncwarp();
        // layer 2: 128 -> 64, lane computes o=lane and o=lane+32
        float a0 = bb2a, a1 = bb2b;
        const float4* h1q = (const float4*)h1s[w];
#pragma unroll
        for (int j4 = 0; j4 < 32; j4++) {
            float4 hv = h1q[j4];
            int jb = j4*4;
            a0 += hv.x*W2s[(jb+0)*H2+lane];  a1 += hv.x*W2s[(jb+0)*H2+lane+32];
            a0 += hv.y*W2s[(jb+1)*H2+lane];  a1 += hv.y*W2s[(jb+1)*H2+lane+32];
            a0 += hv.z*W2s[(jb+2)*H2+lane];  a1 += hv.z*W2s[(jb+2)*H2+lane+32];
            a0 += hv.w*W2s[(jb+3)*H2+lane];  a1 += hv.w*W2s[(jb+3)*H2+lane+32];
        }
        __syncwarp();
        h2s[w][lane]    = fmaxf(a0, 0.0f);
        h2s[w][lane+32] = fmaxf(a1, 0.0f);
        __syncwarp();
        // layer 3: 64 -> 32, lane computes output c=lane
        float a = bb3;
        const float4* h2q = (const float4*)h2s[w];
#pragma unroll
        for (int j4 = 0; j4 < 16; j4++) {
            float4 hv = h2q[j4];
            int jb = j4*4;
            a += hv.x*W3s[(jb+0)*H3+lane];
            a += hv.y*W3s[(jb+1)*H3+lane];
            a += hv.z*W3s[(jb+2)*H3+lane];
            a += hv.w*W3s[(jb+3)*H3+lane];
        }
        a = fmaxf(a, 0.0f);
        mx = fmaxf(mx, a);
        __syncwarp();
    }
    // pool layout [b][p][c=lane][k]
    g_pool[(((size_t)b*PP + p)*H3 + lane)*KPP + k] = mx;
}

// ============================================================
// K4: out[b][j][p] = sum_m pool[b][p][m] * Wr[j][m] + br[j]
// C(512x128) = A(512x864) @ Wr^T ; 32x32 tiles, 2x2/thread
// grid = 16*4 = 64 blocks x 256 threads
// smem padded to EVEN stride 34 so float2 reads stay 8B-aligned
// ============================================================
__global__ void k4_final(const float* __restrict__ Wr,
                         const float* __restrict__ br,
                         float* __restrict__ out) {
    __shared__ __align__(8) float As[32][34];  // [kk][rr], even stride
    __shared__ __align__(8) float Bs[32][34];  // [kk][cc]
    int r0 = (blockIdx.x >> 2) * 32;
    int j0 = (blockIdx.x & 3) * 32;
    int t  = threadIdx.x;
    int lr = t >> 5;        // 0..7 (row/col group for loads)
    int kk = t & 31;
    int ty = t >> 4, tx = t & 15;
    float acc[2][2] = {};

    for (int k0 = 0; k0 < MTOT; k0 += 32) {
        __syncthreads();
#pragma unroll
        for (int i = 0; i < 4; i++) {
            int rr = lr + 8*i;
            As[kk][rr] = g_pool[(size_t)(r0+rr)*MTOT + k0 + kk];
            Bs[kk][rr] = Wr[(size_t)(j0+rr)*MTOT + k0 + kk];
        }
        __syncthreads();
#pragma unroll
        for (int q = 0; q < 32; q++) {
            float2 a  = *(const float2*)&As[q][ty*2];
            float2 bv = *(const float2*)&Bs[q][tx*2];
            acc[0][0] += a.x*bv.x; acc[0][1] += a.x*bv.y;
            acc[1][0] += a.y*bv.x; acc[1][1] += a.y*bv.y;
        }
    }
#pragma unroll
    for (int r = 0; r < 2; r++) {
        int row = r0 + ty*2 + r;
        int b = row >> 8, p = row & 255;
#pragma unroll
        for (int c = 0; c < 2; c++) {
            int j = j0 + tx*2 + c;
            out[(size_t)b*H1*PP + (size_t)j*PP + p] = acc[r][c] + br[j];
        }
    }
}

// ============================================================
extern "C" void kernel_launch(void* const* d_in, const int* in_sizes, int n_in,
                              void* d_out, int out_size) {
    const float* seed_xyz      = (const float*)d_in[0];
    const float* seed_features = (const float*)d_in[1];
    const float* boxes         = (const float*)d_in[2];
    const float* origins       = (const float*)d_in[3];
    const float* heading       = (const float*)d_in[4];
    const float* W1            = (const float*)d_in[5];
    const float* b1            = (const float*)d_in[6];
    const float* W2            = (const float*)d_in[7];
    const float* b2            = (const float*)d_in[8];
    const float* W3            = (const float*)d_in[9];
    const float* b3            = (const float*)d_in[10];
    const float* Wr            = (const float*)d_in[11];
    const float* br            = (const float*)d_in[12];
    float* out = (float*)d_out;

    k1_f1<<<64, 256>>>(seed_features, W1, b1);
    k2_ballquery<<<KP_TOTAL/8, 256>>>(seed_xyz, boxes, origins, heading);
    k3_mlp<<<KP_TOTAL/8, 256>>>(seed_xyz, W1, W2, b2, W3, b3);
    k4_final<<<64, 256>>>(Wr, br, out);
}

// round 4
// speedup vs baseline: 1.0663x; 1.0663x over previous
#include <cuda_runtime.h>

#define BB 2
#define NN 1024
#define CC 256
#define PP 256
#define KPP 27
#define NS 16
#define H1 128
#define H2 64
#define H3 32
#define MTOT (H3*KPP)          // 864
#define RADIUS 0.2f
#define KP_PER_B (PP*KPP)      // 6912
#define KP_TOTAL (BB*KP_PER_B) // 13824

// ---- scratch (no allocation allowed -> device globals) ----
__device__ float g_F1[BB*NN*H1];          // feature @ W1[3:] + b1
__device__ float g_kpts[KP_TOTAL*3];
__device__ int   g_idx[KP_TOTAL*NS];
__device__ int   g_cnt[KP_TOTAL];
__device__ float g_pool[BB*PP*H3*KPP];    // [b][p][c][k]
__device__ float g_W2T[H2*H1];            // W2 transposed: [o][j]
__device__ float g_W3T[H3*H2];            // W3 transposed: [o][j]

// ============================================================
// K0: prep — transpose W2/W3, init out = br (k4 accumulates atomically)
// ============================================================
__global__ void k0_prep(const float* __restrict__ W2,
                        const float* __restrict__ W3,
                        const float* __restrict__ br,
                        float* __restrict__ out) {
    int i = blockIdx.x * blockDim.x + threadIdx.x;  // 0 .. 76k
    if (i < H1*H2) {                       // 8192
        int j = i >> 6, o = i & 63;        // W2[j][o]
        g_W2T[o*H1 + j] = W2[i];
    }
    if (i < H2*H3) {                       // 2048
        int j = i >> 5, o = i & 31;        // W3[j][o]
        g_W3T[o*H2 + j] = W3[i];
    }
    if (i < BB*H1*PP) {                    // 65536
        int j = (i >> 8) & (H1-1);
        out[i] = br[j];
    }
}

// ============================================================
// K1: F1 = feat^T @ W1[3:] + b1, 64x64 tiles, double-buffered prefetch
// ============================================================
__global__ void k1_f1(const float* __restrict__ feat,
                      const float* __restrict__ W1,
                      const float* __restrict__ b1) {
    __shared__ __align__(16) float As[32][64];
    __shared__ __align__(16) float Bs[32][64];
    int bx = blockIdx.x;
    int b  = bx >> 5;
    int nt = (bx & 31) >> 1;
    int jt = bx & 1;
    int n0 = nt * 64, j0 = jt * 64;
    int t  = threadIdx.x;
    int tr = t >> 4, tc = t & 15;
    float acc[4][4] = {};
    float ra[8], rb[8];

    const float* fb = feat + (size_t)b*CC*NN;
#pragma unroll
    for (int i = 0; i < 8; i++) {
        int e = t + 256*i; int cc = e >> 6, nn = e & 63;
        ra[i] = fb[(size_t)cc*NN + n0 + nn];
        rb[i] = W1[(size_t)(3 + cc)*H1 + j0 + nn];
    }
    for (int c0 = 0; c0 < CC; c0 += 32) {
        __syncthreads();
#pragma unroll
        for (int i = 0; i < 8; i++) {
            int e = t + 256*i; int cc = e >> 6, nn = e & 63;
            As[cc][nn] = ra[i];
            Bs[cc][nn] = rb[i];
        }
        __syncthreads();
        if (c0 + 32 < CC) {
#pragma unroll
            for (int i = 0; i < 8; i++) {
                int e = t + 256*i; int cc = e >> 6, nn = e & 63;
                ra[i] = fb[(size_t)(c0+32+cc)*NN + n0 + nn];
                rb[i] = W1[(size_t)(3 + c0+32+cc)*H1 + j0 + nn];
            }
        }
#pragma unroll
        for (int kk = 0; kk < 32; kk++) {
            float4 a = *(const float4*)&As[kk][tr*4];
            float4 w = *(const float4*)&Bs[kk][tc*4];
            float av[4] = {a.x,a.y,a.z,a.w};
            float wv[4] = {w.x,w.y,w.z,w.w};
#pragma unroll
            for (int r = 0; r < 4; r++)
#pragma unroll
                for (int q = 0; q < 4; q++) acc[r][q] += av[r]*wv[q];
        }
    }
#pragma unroll
    for (int r = 0; r < 4; r++) {
        int n = n0 + tr*4 + r;
#pragma unroll
        for (int q = 0; q < 4; q++) {
            int j = j0 + tc*4 + q;
            g_F1[((size_t)b*NN + n)*H1 + j] = acc[r][q] + b1[j];
        }
    }
}

// ============================================================
// K2: keypoints + ball query (first <=16 in index order)
// ============================================================
__global__ void k2_ballquery(const float* __restrict__ seed_xyz,
                             const float* __restrict__ boxes,
                             const float* __restrict__ origins,
                             const float* __restrict__ heading) {
    __shared__ float sx[NN], sy[NN], sz[NN], ssq[NN];
    int b      = blockIdx.x / (KP_PER_B / 8);
    int kpbase = (blockIdx.x % (KP_PER_B / 8)) * 8;
    int t = threadIdx.x;
    for (int i = t; i < NN; i += 256) {
        float x = seed_xyz[((size_t)b*NN + i)*3 + 0];
        float y = seed_xyz[((size_t)b*NN + i)*3 + 1];
        float z = seed_xyz[((size_t)b*NN + i)*3 + 2];
        sx[i]=x; sy[i]=y; sz[i]=z; ssq[i]=x*x+y*y+z*z;
    }
    __syncthreads();

    int w = t >> 5, lane = t & 31;
    int kpid = kpbase + w;
    int g = b*KP_PER_B + kpid;
    int p = kpid / KPP, k = kpid % KPP;

    const float* bx = boxes + ((size_t)b*PP + p)*6;
    float b0=bx[0], b1v=bx[1], b2v=bx[2], b3v=bx[3], b4v=bx[4], b5v=bx[5];
    const float* og = origins + ((size_t)b*PP + p)*3;
    float h = heading[(size_t)b*PP + p];
    int i0 = k/9, i1 = (k/3)%3, i2 = k%3;
    float lx = (i0+0.5f)/3.0f*(b0+b3v) - b0;
    float ly = (i1+0.5f)/3.0f*(b1v+b4v) - b1v;
    float lz = (i2+0.5f)/3.0f*(b2v+b5v) - b2v;
    float ch = cosf(h), sh = sinf(h);
    float px =  lx*ch + ly*sh + og[0];
    float py = -lx*sh + ly*ch + og[1];
    float pz =  lz + og[2];

    float kn2 = px*px + py*py + pz*pz;
    const float r2 = RADIUS*RADIUS;
    unsigned total = 0;
    for (int base = 0; base < NN; base += 32) {
        int n = base + lane;
        float d2 = kn2 + ssq[n] - 2.0f*(px*sx[n] + py*sy[n] + pz*sz[n]);
        bool in = d2 < r2;
        unsigned m = __ballot_sync(0xffffffffu, in);
        if (m && total < 16u) {
            int before = __popc(m & ((1u << lane) - 1u));
            if (in && total + before < 16u)
                g_idx[g*NS + total + before] = n;
        }
        total += __popc(m);
        if (total >= 16u) break;
    }
    if (lane == 0) {
        int stored = total < 16u ? (int)total : 16;
        if (stored == 0) { g_idx[g*NS] = 0; stored = 1; }
        g_cnt[g] = stored;
        g_kpts[g*3+0] = px; g_kpts[g*3+1] = py; g_kpts[g*3+2] = pz;
    }
}

// ============================================================
// K3: fused MLP + maxpool. Transposed weights (conflict-free float4
// row reads, stride 132/68), 4 accumulators per output, 2 kp/warp.
// grid = KP_TOTAL/16 = 864 blocks x 256 threads
// ============================================================
#define W2S 132
#define W3S 68
__global__ void k3_mlp(const float* __restrict__ seed_xyz,
                       const float* __restrict__ W1,
                       const float* __restrict__ b2,
                       const float* __restrict__ b3) {
    __shared__ __align__(16) float W2Ts[H2*W2S];   // 33.8 KB
    __shared__ __align__(16) float W3Ts[H3*W3S];   // 8.7 KB
    __shared__ __align__(16) float h1s[8][H1];
    __shared__ __align__(16) float h2s[8][H2];
    int t = threadIdx.x;
    for (int i = t; i < H2*H1; i += 256) W2Ts[(i>>7)*W2S + (i&127)] = g_W2T[i];
    for (int i = t; i < H3*H2; i += 256) W3Ts[(i>>6)*W3S + (i&63)]  = g_W3T[i];
    __syncthreads();

    int w = t >> 5, lane = t & 31;
    const float* w2a = &W2Ts[lane*W2S];
    const float* w2b = &W2Ts[(lane+32)*W2S];
    const float* w3a = &W3Ts[lane*W3S];

    float w1x[4], w1y[4], w1z[4];
#pragma unroll
    for (int m2 = 0; m2 < 4; m2++) {
        int j = lane + 32*m2;
        w1x[m2] = W1[0*H1 + j];
        w1y[m2] = W1[1*H1 + j];
        w1z[m2] = W1[2*H1 + j];
    }
    float bb2a = b2[lane], bb2b = b2[lane+32];
    float bb3  = b3[lane];
    const float invR = 1.0f / RADIUS;

    for (int it = 0; it < 2; it++) {
        int g = (blockIdx.x * 8 + w) * 2 + it;
        int b = g / KP_PER_B;
        int kpid = g % KP_PER_B;
        int p = kpid / KPP, k = kpid % KPP;

        float kx = g_kpts[g*3+0], ky = g_kpts[g*3+1], kz = g_kpts[g*3+2];
        int cnt = g_cnt[g];
        float mx = -1e30f;

        for (int s = 0; s < cnt; s++) {
            int i = g_idx[g*NS + s];
            const float* sp = seed_xyz + ((size_t)b*NN + i)*3;
            float gx = (sp[0] - kx) * invR;
            float gy = (sp[1] - ky) * invR;
            float gz = (sp[2] - kz) * invR;
            const float* f1p = &g_F1[((size_t)b*NN + i)*H1];
#pragma unroll
            for (int m2 = 0; m2 < 4; m2++) {
                int j = lane + 32*m2;
                float v = f1p[j] + gx*w1x[m2] + gy*w1y[m2] + gz*w1z[m2];
                h1s[w][j] = fmaxf(v, 0.0f);
            }
            __syncwarp();
            // layer 2: 128 -> 64
            float a0x = bb2a, a0y = 0.f, a0z = 0.f, a0w = 0.f;
            float a1x = bb2b, a1y = 0.f, a1z = 0.f, a1w = 0.f;
            const float4* h1q = (const float4*)h1s[w];
#pragma unroll
            for (int j4 = 0; j4 < 32; j4++) {
                float4 h  = h1q[j4];
                float4 wa = *(const float4*)&w2a[j4*4];
                float4 wb = *(const float4*)&w2b[j4*4];
                a0x = fmaf(h.x, wa.x, a0x); a0y = fmaf(h.y, wa.y, a0y);
                a0z = fmaf(h.z, wa.z, a0z); a0w = fmaf(h.w, wa.w, a0w);
                a1x = fmaf(h.x, wb.x, a1x); a1y = fmaf(h.y, wb.y, a1y);
                a1z = fmaf(h.z, wb.z, a1z); a1w = fmaf(h.w, wb.w, a1w);
            }
            __syncwarp();
            h2s[w][lane]    = fmaxf((a0x+a0y)+(a0z+a0w), 0.0f);
            h2s[w][lane+32] = fmaxf((a1x+a1y)+(a1z+a1w), 0.0f);
            __syncwarp();
            // layer 3: 64 -> 32
            float c0 = bb3, c1 = 0.f, c2 = 0.f, c3 = 0.f;
            const float4* h2q = (const float4*)h2s[w];
#pragma unroll
            for (int j4 = 0; j4 < 16; j4++) {
                float4 h  = h2q[j4];
                float4 wv = *(const float4*)&w3a[j4*4];
                c0 = fmaf(h.x, wv.x, c0); c1 = fmaf(h.y, wv.y, c1);
                c2 = fmaf(h.z, wv.z, c2); c3 = fmaf(h.w, wv.w, c3);
            }
            float a = fmaxf((c0+c1)+(c2+c3), 0.0f);
            mx = fmaxf(mx, a);
            __syncwarp();
        }
        g_pool[(((size_t)b*PP + p)*H3 + lane)*KPP + k] = mx;
    }
}

// ============================================================
// K4: out += pool @ Wr^T, split-K=27, atomicAdd merge
// grid = 64 tiles * 27 = 1728 blocks x 256 threads
// ============================================================
__global__ void k4_final(const float* __restrict__ Wr,
                         float* __restrict__ out) {
    __shared__ __align__(8) float As[32][34];
    __shared__ __align__(8) float Bs[32][34];
    int bx = blockIdx.x;
    int kc   = bx % KPP;
    int tile = bx / KPP;
    int r0 = (tile >> 2) * 32;
    int j0 = (tile & 3) * 32;
    int kb = kc * 32;
    int t  = threadIdx.x;
    int lr = t >> 5;
    int kk = t & 31;
    int ty = t >> 4, tx = t & 15;
    float acc[2][2] = {};

#pragma unroll
    for (int i = 0; i < 4; i++) {
        int rr = lr + 8*i;
        As[kk][rr] = g_pool[(size_t)(r0+rr)*MTOT + kb + kk];
        Bs[kk][rr] = Wr[(size_t)(j0+rr)*MTOT + kb + kk];
    }
    __syncthreads();
#pragma unroll
    for (int q = 0; q < 32; q++) {
        float2 a  = *(const float2*)&As[q][ty*2];
        float2 bv = *(const float2*)&Bs[q][tx*2];
        acc[0][0] += a.x*bv.x; acc[0][1] += a.x*bv.y;
        acc[1][0] += a.y*bv.x; acc[1][1] += a.y*bv.y;
    }
#pragma unroll
    for (int r = 0; r < 2; r++) {
        int row = r0 + ty*2 + r;
        int b = row >> 8, p = row & 255;
#pragma unroll
        for (int c = 0; c < 2; c++) {
            int j = j0 + tx*2 + c;
            atomicAdd(&out[(size_t)b*H1*PP + (size_t)j*PP + p], acc[r][c]);
        }
    }
}

// ============================================================
extern "C" void kernel_launch(void* const* d_in, const int* in_sizes, int n_in,
                              void* d_out, int out_size) {
    const float* seed_xyz      = (const float*)d_in[0];
    const float* seed_features = (const float*)d_in[1];
    const float* boxes         = (const float*)d_in[2];
    const float* origins       = (const float*)d_in[3];
    const float* heading       = (const float*)d_in[4];
    const float* W1            = (const float*)d_in[5];
    const float* b1            = (const float*)d_in[6];
    const float* W2            = (const float*)d_in[7];
    const float* b2            = (const float*)d_in[8];
    const float* W3            = (const float*)d_in[9];
    const float* b3            = (const float*)d_in[10];
    const float* Wr            = (const float*)d_in[11];
    const float* br            = (const float*)d_in[12];
    float* out = (float*)d_out;

    k0_prep<<<(BB*H1*PP + 255)/256, 256>>>(W2, W3, br, out);
    k1_f1<<<64, 256>>>(seed_features, W1, b1);
    k2_ballquery<<<KP_TOTAL/8, 256>>>(seed_xyz, boxes, origins, heading);
    k3_mlp<<<KP_TOTAL/16, 256>>>(seed_xyz, W1, b2, b3);
    k4_final<<<64*KPP, 256>>>(Wr, out);
}